// round 3
// baseline (speedup 1.0000x reference)
#include <cuda_runtime.h>

// Inverted window cross-attention, fp32, packed f32x2 FMAs, register softmax.
// One CTA per (window, head): 1024 x 6 = 6144 CTAs, 128 threads.

#define NT 64
#define HD 32
#define PADQ 34        // Q/K pitch: 17t+d/2 distinct mod 32 -> conflict-free LDS/STS.64
#define PADV 36        // V pitch: 16B-aligned rows
#define SROW 66        // attn pitch: PV av loads conflict-free (33*ry mod 32 = ry)

typedef unsigned long long ull;

constexpr int Bc = 4, Hc = 128, Wc = 128, Cc = 192;
constexpr int Lc = Hc * Wc;
constexpr long long BLC = (long long)Bc * Lc * Cc;

__device__ __forceinline__ void fma2(ull& d, ull a, ull b) {
    asm("fma.rn.f32x2 %0, %1, %2, %0;" : "+l"(d) : "l"(a), "l"(b));
}
__device__ __forceinline__ ull pk2(float lo, float hi) {
    ull r; asm("mov.b64 %0, {%1, %2};" : "=l"(r) : "f"(lo), "f"(hi)); return r;
}
__device__ __forceinline__ float2 up2(ull v) {
    float2 f; asm("mov.b64 {%0, %1}, %2;" : "=f"(f.x), "=f"(f.y) : "l"(v)); return f;
}
__device__ __forceinline__ void st4_64(float* p, float4 v) {
    *(float2*)p       = make_float2(v.x, v.y);
    *(float2*)(p + 2) = make_float2(v.z, v.w);
}

__global__ __launch_bounds__(128, 4)
void inv_attn_kernel(const float* __restrict__ qkv1,
                     const float* __restrict__ qkv2,
                     float* __restrict__ out)
{
    extern __shared__ float sm[];
    float* sQ2 = sm;                       // [NT][PADQ]
    float* sK2 = sm + NT * PADQ;
    float* sK1 = sm + 2 * NT * PADQ;
    float* sQ1 = sm + 3 * NT * PADQ;
    float* sV  = sm + 4 * NT * PADQ;       // [NT][PADV]
    float* sS  = sm;                       // attn overlay on Q2+K2 (4224 <= 4352 floats)

    const int tid  = threadIdx.x;
    const int win  = blockIdx.x;
    const int head = blockIdx.y;
    const int b  = win >> 8;
    const int hb = (win >> 4) & 15;
    const int wb = win & 15;
    const int row0  = (hb * 8) * Wc + wb * 8;
    const int cbase = head * HD;

    // ---------------- load: 6 gmem tiles -> 5 smem tiles (conflict-free STS) --------
    {
        const int t  = tid & 63;            // token; within a warp t spans 32 values
        const int dq = (tid >> 6) * 16;     // half of head_dim
        const int hs = t >> 3, ws = t & 7;
        const long long grow = ((long long)b * Lc + row0 + hs * Wc + ws) * Cc + cbase;
        const float* q1g = qkv1 + grow;
        const float* k1g = qkv1 + BLC + grow;
        const float* v1g = qkv1 + 2 * BLC + grow;
        const float* v2g = qkv1 + 3 * BLC + grow;
        const float* q2g = qkv2 + grow;
        const float* k2g = qkv2 + BLC + grow;
#pragma unroll
        for (int k = 0; k < 4; k++) {
            const int d = dq + 4 * k;
            st4_64(sQ2 + t * PADQ + d, *(const float4*)(q2g + d));
            st4_64(sK2 + t * PADQ + d, *(const float4*)(k2g + d));
            st4_64(sK1 + t * PADQ + d, *(const float4*)(k1g + d));
            st4_64(sQ1 + t * PADQ + d, *(const float4*)(q1g + d));
            float4 y = *(const float4*)(v1g + d);
            float4 z = *(const float4*)(v2g + d);
            y.x += z.x; y.y += z.y; y.z += z.z; y.w += z.w;
            *(float4*)(sV + t * PADV + d) = y;
        }
    }
    __syncthreads();

    // ---------------- scores (8x4 reg tile) + register softmax ----------------
    {
        const int ty = tid >> 4;   // 0..7  -> rows ty + 8*i
        const int tx = tid & 15;   // 0..15 -> cols tx + 16*j (row's 64 cols live in 1 warp)
        ull acc[8][4] = {};
#pragma unroll 4
        for (int d = 0; d < HD; d += 2) {
            ull a[8], bb[4];
#pragma unroll
            for (int i = 0; i < 8; i++) a[i] = *(const ull*)(sQ2 + (ty + 8 * i) * PADQ + d);
#pragma unroll
            for (int j = 0; j < 4; j++) bb[j] = *(const ull*)(sK1 + (tx + 16 * j) * PADQ + d);
#pragma unroll
            for (int i = 0; i < 8; i++)
#pragma unroll
                for (int j = 0; j < 4; j++) fma2(acc[i][j], a[i], bb[j]);
#pragma unroll
            for (int i = 0; i < 8; i++) a[i] = *(const ull*)(sK2 + (ty + 8 * i) * PADQ + d);
#pragma unroll
            for (int j = 0; j < 4; j++) bb[j] = *(const ull*)(sQ1 + (tx + 16 * j) * PADQ + d);
#pragma unroll
            for (int i = 0; i < 8; i++)
#pragma unroll
                for (int j = 0; j < 4; j++) fma2(acc[i][j], a[i], bb[j]);
        }

        // exp (max-sub safely skipped: scores bounded), row-sum via shfl, fold 1/sum
        const float scale = 0.17677669529663687f;  // 32^-0.5
        float e[8][4];
        float inv[8];
#pragma unroll
        for (int i = 0; i < 8; i++) {
#pragma unroll
            for (int j = 0; j < 4; j++) {
                float2 f = up2(acc[i][j]);
                e[i][j] = __expf(2.0f - scale * (f.x + f.y));
            }
            float r = (e[i][0] + e[i][1]) + (e[i][2] + e[i][3]);
            r += __shfl_xor_sync(0xffffffffu, r, 1);
            r += __shfl_xor_sync(0xffffffffu, r, 2);
            r += __shfl_xor_sync(0xffffffffu, r, 4);
            r += __shfl_xor_sync(0xffffffffu, r, 8);
            inv[i] = 1.0f / r;
        }

        __syncthreads();   // all warps done reading Q2/K2 -> safe to overlay attn
#pragma unroll
        for (int i = 0; i < 8; i++)
#pragma unroll
            for (int j = 0; j < 4; j++)
                sS[(ty + 8 * i) * SROW + tx + 16 * j] = e[i][j] * inv[i];
    }
    __syncthreads();

    // ---------------- PV: rows {ry, ry+32} x 8-float d-slice per thread ------------
    {
        const int ry = tid >> 2;            // 0..31
        const int dd = (tid & 3) * 8;       // d-slice start (8 floats)
        ull o[2][4] = {};
        const float* a0p = sS + ry * SROW;
        const float* a1p = sS + (ry + 32) * SROW;
#pragma unroll 4
        for (int m = 0; m < NT; m += 2) {
            const ull av0 = *(const ull*)(a0p + m);   // attn[ry][m..m+1]
            const ull av1 = *(const ull*)(a1p + m);   // attn[ry+32][m..m+1]
            const ulonglong2 va = *(const ulonglong2*)(sV + m * PADV + dd);
            const ulonglong2 vb = *(const ulonglong2*)(sV + m * PADV + dd + 4);
            const ulonglong2 vc = *(const ulonglong2*)(sV + (m + 1) * PADV + dd);
            const ulonglong2 vd = *(const ulonglong2*)(sV + (m + 1) * PADV + dd + 4);
            const float2 f0 = up2(av0), f1 = up2(av1);
            const ull s00 = pk2(f0.x, f0.x), s01 = pk2(f0.y, f0.y);
            const ull s10 = pk2(f1.x, f1.x), s11 = pk2(f1.y, f1.y);
            fma2(o[0][0], s00, va.x); fma2(o[0][1], s00, va.y);
            fma2(o[0][2], s00, vb.x); fma2(o[0][3], s00, vb.y);
            fma2(o[0][0], s01, vc.x); fma2(o[0][1], s01, vc.y);
            fma2(o[0][2], s01, vd.x); fma2(o[0][3], s01, vd.y);
            fma2(o[1][0], s10, va.x); fma2(o[1][1], s10, va.y);
            fma2(o[1][2], s10, vb.x); fma2(o[1][3], s10, vb.y);
            fma2(o[1][0], s11, vc.x); fma2(o[1][1], s11, vc.y);
            fma2(o[1][2], s11, vd.x); fma2(o[1][3], s11, vd.y);
        }
#pragma unroll
        for (int r = 0; r < 2; r++) {
            const int n = ry + 32 * r;
            const long long g =
                ((long long)b * Lc + row0 + (n >> 3) * Wc + (n & 7)) * Cc + cbase + dd;
            const float2 p0 = up2(o[r][0]), p1 = up2(o[r][1]);
            const float2 p2 = up2(o[r][2]), p3 = up2(o[r][3]);
            *(float4*)(out + g)     = make_float4(p0.x, p0.y, p1.x, p1.y);
            *(float4*)(out + g + 4) = make_float4(p2.x, p2.y, p3.x, p3.y);
        }
    }
}

extern "C" void kernel_launch(void* const* d_in, const int* in_sizes, int n_in,
                              void* d_out, int out_size)
{
    const float* qkv1 = (const float*)d_in[0];
    const float* qkv2 = (const float*)d_in[1];
    float* out = (float*)d_out;

    const int smem_bytes = (4 * NT * PADQ + NT * PADV) * (int)sizeof(float);  // 44032
    cudaFuncSetAttribute(inv_attn_kernel,
                         cudaFuncAttributeMaxDynamicSharedMemorySize, smem_bytes);
    inv_attn_kernel<<<dim3(1024, 6, 1), 128, smem_bytes>>>(qkv1, qkv2, out);
}

// round 4
// speedup vs baseline: 1.3554x; 1.3554x over previous
#include <cuda_runtime.h>

// Inverted window cross-attention, fp32, packed f32x2 FMAs.
// One CTA per (window, head): 1024 x 6 = 6144 CTAs, 128 threads.
// R4: R2 structure with LDS.128-vectorized score (d-step 4) and PV (m-step 4).

#define NT 64
#define HD 32
#define PADQ 36        // Q/K pitch: 16B-aligned rows; bb phases conflict-free
#define PADV 36        // V pitch: 16B-aligned rows
#define SROW 68        // attn pitch: 16B-aligned rows for float4 PV loads

typedef unsigned long long ull;

constexpr int Bc = 4, Hc = 128, Wc = 128, Cc = 192;
constexpr int Lc = Hc * Wc;
constexpr long long BLC = (long long)Bc * Lc * Cc;

__device__ __forceinline__ void fma2(ull& d, ull a, ull b) {
    asm("fma.rn.f32x2 %0, %1, %2, %0;" : "+l"(d) : "l"(a), "l"(b));
}
__device__ __forceinline__ ull pk2(float lo, float hi) {
    ull r; asm("mov.b64 %0, {%1, %2};" : "=l"(r) : "f"(lo), "f"(hi)); return r;
}
__device__ __forceinline__ float2 up2(ull v) {
    float2 f; asm("mov.b64 {%0, %1}, %2;" : "=f"(f.x), "=f"(f.y) : "l"(v)); return f;
}

__global__ __launch_bounds__(128, 4)
void inv_attn_kernel(const float* __restrict__ qkv1,
                     const float* __restrict__ qkv2,
                     float* __restrict__ out)
{
    extern __shared__ float sm[];
    float* sQ2 = sm;                       // [NT][PADQ]
    float* sK2 = sm + NT * PADQ;
    float* sK1 = sm + 2 * NT * PADQ;
    float* sQ1 = sm + 3 * NT * PADQ;
    float* sV  = sm + 4 * NT * PADQ;       // [NT][PADV]
    float* sInv = sV + NT * PADV;          // [NT]
    float* sS  = sm;                       // attn overlay on Q2+K2: 64*68=4352 <= 4608

    const int tid  = threadIdx.x;
    const int win  = blockIdx.x;
    const int head = blockIdx.y;
    const int b  = win >> 8;
    const int hb = (win >> 4) & 15;
    const int wb = win & 15;
    const int row0  = (hb * 8) * Wc + wb * 8;
    const int cbase = head * HD;

    // ---------------- load: 6 gmem tiles -> 5 smem tiles (STS.128) ----------------
    {
        const int t  = tid >> 1;            // token 0..63
        const int d0 = (tid & 1) * 16;      // half of head_dim
        const int hs = t >> 3, ws = t & 7;
        const long long grow = ((long long)b * Lc + row0 + hs * Wc + ws) * Cc + cbase;
        const float* q1g = qkv1 + grow;
        const float* k1g = qkv1 + BLC + grow;
        const float* v1g = qkv1 + 2 * BLC + grow;
        const float* v2g = qkv1 + 3 * BLC + grow;
        const float* q2g = qkv2 + grow;
        const float* k2g = qkv2 + BLC + grow;
#pragma unroll
        for (int k = 0; k < 4; k++) {
            const int d = d0 + 4 * k;
            *(float4*)(sQ2 + t * PADQ + d) = *(const float4*)(q2g + d);
            *(float4*)(sK2 + t * PADQ + d) = *(const float4*)(k2g + d);
            *(float4*)(sK1 + t * PADQ + d) = *(const float4*)(k1g + d);
            *(float4*)(sQ1 + t * PADQ + d) = *(const float4*)(q1g + d);
            float4 y = *(const float4*)(v1g + d);
            float4 z = *(const float4*)(v2g + d);
            y.x += z.x; y.y += z.y; y.z += z.z; y.w += z.w;
            *(float4*)(sV + t * PADV + d) = y;
        }
    }
    __syncthreads();

    // ---------------- scores: 8x4 register tile, d-step 4 (LDS.128) ----------------
    {
        const int ty = tid >> 4;   // 0..7  -> rows ty + 8*i
        const int tx = tid & 15;   // 0..15 -> cols tx + 16*j
        ull acc[8][4] = {};
#pragma unroll
        for (int d = 0; d < HD; d += 4) {
            ulonglong2 bb[4];
#pragma unroll
            for (int j = 0; j < 4; j++)
                bb[j] = *(const ulonglong2*)(sK1 + (tx + 16 * j) * PADQ + d);
#pragma unroll
            for (int i = 0; i < 8; i++) {
                const ulonglong2 a = *(const ulonglong2*)(sQ2 + (ty + 8 * i) * PADQ + d);
#pragma unroll
                for (int j = 0; j < 4; j++) {
                    fma2(acc[i][j], a.x, bb[j].x);
                    fma2(acc[i][j], a.y, bb[j].y);
                }
            }
#pragma unroll
            for (int j = 0; j < 4; j++)
                bb[j] = *(const ulonglong2*)(sQ1 + (tx + 16 * j) * PADQ + d);
#pragma unroll
            for (int i = 0; i < 8; i++) {
                const ulonglong2 a = *(const ulonglong2*)(sK2 + (ty + 8 * i) * PADQ + d);
#pragma unroll
                for (int j = 0; j < 4; j++) {
                    fma2(acc[i][j], a.x, bb[j].x);
                    fma2(acc[i][j], a.y, bb[j].y);
                }
            }
        }
        __syncthreads();   // Q2/K2 fully consumed -> safe to overlay scores
        const float scale = 0.17677669529663687f;  // 32^-0.5
#pragma unroll
        for (int i = 0; i < 8; i++)
#pragma unroll
            for (int j = 0; j < 4; j++) {
                float2 f = up2(acc[i][j]);
                sS[(ty + 8 * i) * SROW + tx + 16 * j] = 2.0f - scale * (f.x + f.y);
            }
    }
    __syncthreads();

    // ---------------- softmax (R2-style; 1/sum folded into PV epilogue) ----------------
    {
        const int row = tid >> 1;
        const int seg = tid & 1;
        float* rp = sS + row * SROW + seg * 32;
        ull u[16];
#pragma unroll
        for (int k = 0; k < 16; k++) u[k] = *(const ull*)(rp + 2 * k);
        float mx = -1e30f;
#pragma unroll
        for (int k = 0; k < 16; k++) {
            float2 f = up2(u[k]);
            mx = fmaxf(mx, fmaxf(f.x, f.y));
        }
        mx = fmaxf(mx, __shfl_xor_sync(0xffffffffu, mx, 1));
        float sum = 0.f;
#pragma unroll
        for (int k = 0; k < 16; k++) {
            float2 f = up2(u[k]);
            float e0 = __expf(f.x - mx);
            float e1 = __expf(f.y - mx);
            sum += e0 + e1;
            *(ull*)(rp + 2 * k) = pk2(e0, e1);
        }
        sum += __shfl_xor_sync(0xffffffffu, sum, 1);
        if (!seg) sInv[row] = 1.0f / sum;
    }
    __syncthreads();

    // ---------------- PV: 4 rows x 4-float d-slice per thread, m-step 4 ----------------
    {
        const int ty2 = tid >> 3;       // 0..15 -> rows ty2 + 16*i
        const int tx2 = tid & 7;        // 0..7  -> dd = 4*tx2
        const int dd = tx2 * 4;
        ull o[4][2] = {};
#pragma unroll 4
        for (int m = 0; m < NT; m += 4) {
            float4 av[4];
#pragma unroll
            for (int i = 0; i < 4; i++)
                av[i] = *(const float4*)(sS + (ty2 + 16 * i) * SROW + m);
            ulonglong2 v[4];
#pragma unroll
            for (int p = 0; p < 4; p++)
                v[p] = *(const ulonglong2*)(sV + (m + p) * PADV + dd);
#pragma unroll
            for (int i = 0; i < 4; i++) {
                const float w0 = av[i].x, w1 = av[i].y, w2 = av[i].z, w3 = av[i].w;
                const ull s0 = pk2(w0, w0), s1 = pk2(w1, w1);
                const ull s2 = pk2(w2, w2), s3 = pk2(w3, w3);
                fma2(o[i][0], s0, v[0].x); fma2(o[i][1], s0, v[0].y);
                fma2(o[i][0], s1, v[1].x); fma2(o[i][1], s1, v[1].y);
                fma2(o[i][0], s2, v[2].x); fma2(o[i][1], s2, v[2].y);
                fma2(o[i][0], s3, v[3].x); fma2(o[i][1], s3, v[3].y);
            }
        }
#pragma unroll
        for (int i = 0; i < 4; i++) {
            const int n = ty2 + 16 * i;
            const float inv = sInv[n];
            const float2 p = up2(o[i][0]);
            const float2 q = up2(o[i][1]);
            const long long g =
                ((long long)b * Lc + row0 + (n >> 3) * Wc + (n & 7)) * Cc + cbase + dd;
            *(float4*)(out + g) = make_float4(p.x * inv, p.y * inv, q.x * inv, q.y * inv);
        }
    }
}

extern "C" void kernel_launch(void* const* d_in, const int* in_sizes, int n_in,
                              void* d_out, int out_size)
{
    const float* qkv1 = (const float*)d_in[0];
    const float* qkv2 = (const float*)d_in[1];
    float* out = (float*)d_out;

    const int smem_bytes = (4 * NT * PADQ + NT * PADV + NT) * (int)sizeof(float);  // 46336
    cudaFuncSetAttribute(inv_attn_kernel,
                         cudaFuncAttributeMaxDynamicSharedMemorySize, smem_bytes);
    inv_attn_kernel<<<dim3(1024, 6, 1), 128, smem_bytes>>>(qkv1, qkv2, out);
}

// round 6
// speedup vs baseline: 2.3609x; 1.7418x over previous
#include <cuda_runtime.h>
#include <cuda_bf16.h>
#include <cstdint>

// Inverted window cross-attention via warp-level bf16 mma.sync (sm_80+ ISA,
// legal at compute_103). One CTA per (window, head): 1024 x 6 CTAs, 128 thr.
// S(64x64) = q2.k1^T + k2.q1^T with bf16 2-way split (3 terms per product);
// softmax entirely in registers; PV = [e_hi,e_lo] x [vh,vl] (3 terms).

typedef unsigned long long ull;

constexpr int Bc = 4, Hc = 128, Wc = 128, Cc = 192;
constexpr int Lc = Hc * Wc;
constexpr long long BLC = (long long)Bc * Lc * Cc;

constexpr int PITCH = 72;                 // bf16 elems per smem row (144B: conflict-free 8-row ldmatrix)
// smem byte offsets: 5 tiles of 64 x 72 bf16 (cols 0-31 = hi, 32-63 = lo)
constexpr int SQ2 = 0, SK2 = 9216, SK1 = 18432, SQ1 = 27648, SV = 36864;
constexpr int SMEM_TOTAL = 46080;

__device__ __forceinline__ uint32_t smem_u32(const void* p) {
    uint32_t a;
    asm("{ .reg .u64 t; cvta.to.shared.u64 t, %1; cvt.u32.u64 %0, t; }" : "=r"(a) : "l"(p));
    return a;
}
__device__ __forceinline__ uint32_t pack_bf16(float lo, float hi) {
    uint32_t r; asm("cvt.rn.bf16x2.f32 %0, %1, %2;" : "=r"(r) : "f"(hi), "f"(lo)); return r;
}
__device__ __forceinline__ float bf_lo(uint32_t p) { return __uint_as_float(p << 16); }
__device__ __forceinline__ float bf_hi(uint32_t p) { return __uint_as_float(p & 0xffff0000u); }

// split 8 floats -> hi uint4 + lo uint4 (bf16x2, element k at lower bits of pair)
__device__ __forceinline__ void split8(const float* x, uint4& h, uint4& l) {
    uint32_t h0 = pack_bf16(x[0], x[1]), h1 = pack_bf16(x[2], x[3]);
    uint32_t h2 = pack_bf16(x[4], x[5]), h3 = pack_bf16(x[6], x[7]);
    h = make_uint4(h0, h1, h2, h3);
    l = make_uint4(pack_bf16(x[0]-bf_lo(h0), x[1]-bf_hi(h0)),
                   pack_bf16(x[2]-bf_lo(h1), x[3]-bf_hi(h1)),
                   pack_bf16(x[4]-bf_lo(h2), x[5]-bf_hi(h2)),
                   pack_bf16(x[6]-bf_lo(h3), x[7]-bf_hi(h3)));
}

__device__ __forceinline__ void ldsm4(uint32_t* r, uint32_t a) {
    asm volatile("ldmatrix.sync.aligned.m8n8.x4.shared.b16 {%0,%1,%2,%3}, [%4];"
                 : "=r"(r[0]), "=r"(r[1]), "=r"(r[2]), "=r"(r[3]) : "r"(a));
}
__device__ __forceinline__ void ldsm4t(uint32_t* r, uint32_t a) {
    asm volatile("ldmatrix.sync.aligned.m8n8.x4.trans.shared.b16 {%0,%1,%2,%3}, [%4];"
                 : "=r"(r[0]), "=r"(r[1]), "=r"(r[2]), "=r"(r[3]) : "r"(a));
}
__device__ __forceinline__ void mma16816(float* d, const uint32_t* a, const uint32_t* b) {
    asm volatile("mma.sync.aligned.m16n8k16.row.col.f32.bf16.bf16.f32 "
                 "{%0,%1,%2,%3}, {%4,%5,%6,%7}, {%8,%9}, {%0,%1,%2,%3};"
                 : "+f"(d[0]), "+f"(d[1]), "+f"(d[2]), "+f"(d[3])
                 : "r"(a[0]), "r"(a[1]), "r"(a[2]), "r"(a[3]), "r"(b[0]), "r"(b[1]));
}

__global__ __launch_bounds__(128, 4)
void inv_attn_mma(const float* __restrict__ qkv1,
                  const float* __restrict__ qkv2,
                  float* __restrict__ out)
{
    extern __shared__ char sm[];
    const int tid  = threadIdx.x;
    const int lane = tid & 31, wid = tid >> 5;

    const int win = blockIdx.x, head = blockIdx.y;
    const int b = win >> 8, hb = (win >> 4) & 15, wb = win & 15;
    const int row0  = hb * 8 * Wc + wb * 8;
    const int cbase = head * 32;

    // ---------------- loader: fp32 -> bf16 hi/lo split tiles ----------------
    {
        const int t  = tid >> 1;            // token 0..63
        const int dh = (tid & 1) * 16;      // half of head_dim
        const long long gt = ((long long)b * Lc + row0 + (t >> 3) * Wc + (t & 7)) * Cc + cbase;
        const float* srcs[4] = { qkv2 + gt,            // q2 -> SQ2
                                 qkv2 + BLC + gt,      // k2 -> SK2
                                 qkv1 + BLC + gt,      // k1 -> SK1
                                 qkv1 + gt };          // q1 -> SQ1
        const int dsts[4] = { SQ2, SK2, SK1, SQ1 };
#pragma unroll
        for (int s = 0; s < 4; s++) {
            const float* g = srcs[s];
            char* dbase = sm + dsts[s] + t * (PITCH * 2);
#pragma unroll
            for (int j = 0; j < 2; j++) {
                const int d = dh + 8 * j;
                float x[8]; uint4 h, l;
                *(float4*)(x)     = *(const float4*)(g + d);
                *(float4*)(x + 4) = *(const float4*)(g + d + 4);
                split8(x, h, l);
                *(uint4*)(dbase + d * 2)        = h;
                *(uint4*)(dbase + (32 + d) * 2) = l;
            }
        }
        // V = v1 + v2, token-major (trans-ldmatrix consumes it)
        const float* v1g = qkv1 + 2 * BLC + gt;
        const float* v2g = qkv1 + 3 * BLC + gt;
        char* dv = sm + SV + t * (PITCH * 2);
#pragma unroll
        for (int j = 0; j < 2; j++) {
            const int d = dh + 8 * j;
            float x[8]; uint4 h, l;
            float4 p = *(const float4*)(v1g + d), q = *(const float4*)(v2g + d);
            x[0] = p.x + q.x; x[1] = p.y + q.y; x[2] = p.z + q.z; x[3] = p.w + q.w;
            p = *(const float4*)(v1g + d + 4); q = *(const float4*)(v2g + d + 4);
            x[4] = p.x + q.x; x[5] = p.y + q.y; x[6] = p.z + q.z; x[7] = p.w + q.w;
            split8(x, h, l);
            *(uint4*)(dv + d * 2)        = h;
            *(uint4*)(dv + (32 + d) * 2) = l;
        }
    }
    __syncthreads();

    const uint32_t smb = smem_u32(sm);
    const int mat = lane >> 3, li = lane & 7;
    const int r0 = wid * 16;

    // lane address parts
    // A (non-trans): mat0 rows r0..r0+7 col c, mat1 rows+8 col c, mat2 rows col c+8, mat3 rows+8 col c+8
    const uint32_t aPart = ((r0 + li + ((mat & 1) << 3)) * PITCH + ((mat >> 1) << 3)) * 2;
    // B score (non-trans): mat0 rows m col c, mat1 rows m col c+8, mat2 col c+32, mat3 col c+40
    const uint32_t bPart = (li * PITCH + ((mat & 1) << 3) + ((mat >> 1) << 5)) * 2;
    // V (trans): mat0 tok rows col c, mat1 tok+8 col c, mat2 rows col c+32, mat3 tok+8 col c+32
    const uint32_t vPart = ((li + ((mat & 1) << 3)) * PITCH + ((mat >> 1) << 5)) * 2;

    // ---------------- score MMAs ----------------
    uint32_t aQh[2][4], aQl[2][4], aKh[2][4], aKl[2][4];
#pragma unroll
    for (int kc = 0; kc < 2; kc++) {
        ldsm4(aQh[kc], smb + SQ2 + aPart + (16 * kc) * 2);
        ldsm4(aQl[kc], smb + SQ2 + aPart + (32 + 16 * kc) * 2);
        ldsm4(aKh[kc], smb + SK2 + aPart + (16 * kc) * 2);
        ldsm4(aKl[kc], smb + SK2 + aPart + (32 + 16 * kc) * 2);
    }
    float sacc[8][4] = {};
#pragma unroll
    for (int j = 0; j < 8; j++) {
#pragma unroll
        for (int kc = 0; kc < 2; kc++) {
            uint32_t bk[4], bq[4];
            const uint32_t off = (j * 8 * PITCH + 16 * kc) * 2;
            ldsm4(bk, smb + SK1 + bPart + off);     // {k1h, k1l}
            ldsm4(bq, smb + SQ1 + bPart + off);     // {q1h, q1l}
            mma16816(sacc[j], aQh[kc], bk);         // q2h.k1h
            mma16816(sacc[j], aQl[kc], bk);         // q2l.k1h
            mma16816(sacc[j], aQh[kc], bk + 2);     // q2h.k1l
            mma16816(sacc[j], aKh[kc], bq);         // k2h.q1h
            mma16816(sacc[j], aKl[kc], bq);         // k2l.q1h
            mma16816(sacc[j], aKh[kc], bq + 2);     // k2h.q1l
        }
    }

    // ---------------- register softmax ----------------
    const float scale = 0.17677669529663687f;  // 32^-0.5
    float e[8][4];
    float s0 = 0.f, s1 = 0.f;
#pragma unroll
    for (int j = 0; j < 8; j++) {
        e[j][0] = __expf(2.f - scale * sacc[j][0]);
        e[j][1] = __expf(2.f - scale * sacc[j][1]);
        e[j][2] = __expf(2.f - scale * sacc[j][2]);
        e[j][3] = __expf(2.f - scale * sacc[j][3]);
        s0 += e[j][0] + e[j][1];
        s1 += e[j][2] + e[j][3];
    }
    s0 += __shfl_xor_sync(0xffffffffu, s0, 1);
    s0 += __shfl_xor_sync(0xffffffffu, s0, 2);
    s1 += __shfl_xor_sync(0xffffffffu, s1, 1);
    s1 += __shfl_xor_sync(0xffffffffu, s1, 2);
    const float inv0 = 1.0f / s0, inv1 = 1.0f / s1;

    // D-fragment -> A-fragment repack with bf16 split (pure register work)
    uint32_t ehi[4][4], elo[4][4];
#pragma unroll
    for (int kc = 0; kc < 4; kc++) {
        const float* t0 = e[2 * kc];
        const float* t1 = e[2 * kc + 1];
        uint32_t h;
        h = pack_bf16(t0[0], t0[1]); ehi[kc][0] = h;
        elo[kc][0] = pack_bf16(t0[0] - bf_lo(h), t0[1] - bf_hi(h));
        h = pack_bf16(t0[2], t0[3]); ehi[kc][1] = h;
        elo[kc][1] = pack_bf16(t0[2] - bf_lo(h), t0[3] - bf_hi(h));
        h = pack_bf16(t1[0], t1[1]); ehi[kc][2] = h;
        elo[kc][2] = pack_bf16(t1[0] - bf_lo(h), t1[1] - bf_hi(h));
        h = pack_bf16(t1[2], t1[3]); ehi[kc][3] = h;
        elo[kc][3] = pack_bf16(t1[2] - bf_lo(h), t1[3] - bf_hi(h));
    }

    // ---------------- PV MMAs ----------------
    float oacc[4][4] = {};
#pragma unroll
    for (int t = 0; t < 4; t++) {
#pragma unroll
        for (int kc = 0; kc < 4; kc++) {
            uint32_t bv[4];
            ldsm4t(bv, smb + SV + vPart + (16 * kc * PITCH + 8 * t) * 2);  // {vh, vl}
            mma16816(oacc[t], ehi[kc], bv);         // ehi.vh
            mma16816(oacc[t], ehi[kc], bv + 2);     // ehi.vl
            mma16816(oacc[t], elo[kc], bv);         // elo.vh
        }
    }

    // ---------------- output (1/sum folded) ----------------
    {
        const int r  = lane >> 2;
        const int cq = (lane & 3) * 2;
        const int nA = r0 + r, nB = nA + 8;
        const long long gA = ((long long)b * Lc + row0 + (nA >> 3) * Wc + (nA & 7)) * Cc + cbase;
        const long long gB = ((long long)b * Lc + row0 + (nB >> 3) * Wc + (nB & 7)) * Cc + cbase;
#pragma unroll
        for (int t = 0; t < 4; t++) {
            *(float2*)(out + gA + 8 * t + cq) = make_float2(oacc[t][0] * inv0, oacc[t][1] * inv0);
            *(float2*)(out + gB + 8 * t + cq) = make_float2(oacc[t][2] * inv1, oacc[t][3] * inv1);
        }
    }
}

extern "C" void kernel_launch(void* const* d_in, const int* in_sizes, int n_in,
                              void* d_out, int out_size)
{
    const float* qkv1 = (const float*)d_in[0];
    const float* qkv2 = (const float*)d_in[1];
    float* out = (float*)d_out;

    cudaFuncSetAttribute(inv_attn_mma,
                         cudaFuncAttributeMaxDynamicSharedMemorySize, SMEM_TOTAL);
    inv_attn_mma<<<dim3(1024, 6, 1), 128, SMEM_TOTAL>>>(qkv1, qkv2, out);
}